// round 9
// baseline (speedup 1.0000x reference)
#include <cuda_runtime.h>

// GaussianBlur v4 (vertical-first, streaming ring, 6 CTA/SM):
// depthwise 21x21 Gaussian (sigma=5), reflect pad 10,
// [32,3,512,512] fp32 = 96 independent 512x512 images.
// Tile 128x64 outputs, 256 threads:
//   phase 1: VERTICAL 21-tap from gmem, 24-register sliding ring (QROWS=32
//            outputs/task, prefetch distance 4, dense coalesced column loads)
//            -> 37.9KB smem (148-wide rows for the x halo).
//   phase 2: HORIZONTAL 21-tap from smem. 4-output windows (6x LDS.128,
//            start-stride 4 floats => conflict-free banking), dense STG.128.

#define W_ 512
#define H_ 512
#define NIMG 96
#define PAD 10

#define TX 128
#define TY 64
#define VCOLS   148                 // TX + 2*PAD
#define VSTRIDE 148                 // floats per smem row (592B, 16B-aligned)
#define QROWS   32                  // v-pass outputs per task
#define VWIN    (QROWS + 2 * PAD)   // 52 rows read per task
#define NTASK1  (VCOLS * (TY / QROWS))   // 296

// 1D separable weights (validated): exp(-(d^2)/50) / 12.089199128
#define KW_INIT const float KW[21] = { \
    0.01119473f, 0.01636989f, 0.02299883f, 0.03104516f, 0.04026340f, \
    0.05017128f, 0.06006594f, 0.06909227f, 0.07635877f, 0.08108053f, \
    0.08271847f, \
    0.08108053f, 0.07635877f, 0.06909227f, 0.06006594f, 0.05017128f, \
    0.04026340f, 0.03104516f, 0.02299883f, 0.01636989f, 0.01119473f }

__device__ __forceinline__ int reflect512(int i) {
    // jnp.pad mode="reflect": -k -> k, 511+k -> 511-k (single reflection)
    i = (i < 0) ? -i : i;
    return (i > 511) ? (1022 - i) : i;
}

// ---- Phase-1 task body: vertical conv of one column strip -----------------
// 24-register ring: preload rows 0..23; at output rr use rows rr..rr+20
// (slots (rr+k)%24), then refill slot rr%24 with row rr+24 (dead row rr).
// All indices compile-time after unroll => no shift moves, ~32 live regs.
template<bool INTERIOR>
__device__ __forceinline__ void vtask_body(const float* __restrict__ img,
                                           float* __restrict__ dst,
                                           int yb, int gx) {
    KW_INIT;
    const float* __restrict__ p =
        img + (size_t)(INTERIOR ? yb : 0) * W_ + gx;

    float v[24];
    #pragma unroll
    for (int j = 0; j < 24; ++j)
        v[j] = INTERIOR ? p[j * W_]
                        : img[(size_t)reflect512(yb + j) * W_ + gx];

    #pragma unroll
    for (int rr = 0; rr < QROWS; ++rr) {
        float a = 0.f;
        #pragma unroll
        for (int k = 0; k < 21; ++k)
            a = fmaf(KW[k], v[(rr + k) % 24], a);
        dst[rr * VSTRIDE] = a;                    // conflict-free STS
        if (rr < VWIN - 24) {                     // rows 24..51
            const int j = rr + 24;
            v[rr % 24] = INTERIOR ? p[j * W_]
                                  : img[(size_t)reflect512(yb + j) * W_ + gx];
        }
    }
}

// Cold path (y-border tiles only): keep it out of the hot instruction stream.
__device__ __noinline__ void vtask_border(const float* __restrict__ img,
                                          float* __restrict__ dst,
                                          int yb, int gx) {
    vtask_body<false>(img, dst, yb, gx);
}

__global__ __launch_bounds__(256, 6)
void blur_v4(const float* __restrict__ in, float* __restrict__ out) {
    KW_INIT;
    __shared__ __align__(16) float Vs[TY * VSTRIDE];   // 37888 B

    const int n   = blockIdx.z;
    const int x0  = blockIdx.x * TX;
    const int y0  = blockIdx.y * TY;
    const int tid = threadIdx.x;

    const float* __restrict__ img = in + (size_t)n * (H_ * W_);

    // ---- Phase 1: vertical conv, gmem -> Vs (296 tasks over 256 threads) --
    #pragma unroll 1
    for (int tau = tid; tau < NTASK1; tau += 256) {
        const int q  = (tau >= VCOLS) ? 1 : 0;     // NTASK1 == 2*VCOLS
        const int c  = tau - q * VCOLS;
        const int gx = reflect512(x0 - PAD + c);
        const int yb = y0 + q * QROWS - PAD;
        float* dst = Vs + (q * QROWS) * VSTRIDE + c;
        if (yb >= 0 && yb + VWIN - 1 < H_)
            vtask_body<true>(img, dst, yb, gx);
        else
            vtask_border(img, dst, yb, gx);
    }
    __syncthreads();

    // ---- Phase 2: horizontal conv, Vs -> gmem -----------------------------
    // Warp = one row (stride 8), lane g covers outputs [4g..4g+3] from window
    // Vs[r][4g..4g+23]: 6x LDS.128 at 16B-stride starts -> conflict-free
    // phases; STG.128 dense.
    float* __restrict__ outimg = out + (size_t)n * (H_ * W_);
    const int g  = tid & 31;
    const int r0 = tid >> 5;

    #pragma unroll
    for (int i = 0; i < 8; ++i) {
        const int r = r0 + i * 8;
        const float* __restrict__ src = Vs + r * VSTRIDE + 4 * g;

        float wv[24];
        #pragma unroll
        for (int j = 0; j < 6; ++j) {
            float4 t = *reinterpret_cast<const float4*>(src + 4 * j);
            wv[4 * j + 0] = t.x; wv[4 * j + 1] = t.y;
            wv[4 * j + 2] = t.z; wv[4 * j + 3] = t.w;
        }

        float h0 = 0.f, h1 = 0.f, h2 = 0.f, h3 = 0.f;
        #pragma unroll
        for (int k = 0; k < 21; ++k) {
            const float w = KW[k];
            h0 = fmaf(w, wv[k + 0], h0);
            h1 = fmaf(w, wv[k + 1], h1);
            h2 = fmaf(w, wv[k + 2], h2);
            h3 = fmaf(w, wv[k + 3], h3);
        }
        *reinterpret_cast<float4*>(outimg + (size_t)(y0 + r) * W_ + x0 + 4 * g)
            = make_float4(h0, h1, h2, h3);
    }
}

extern "C" void kernel_launch(void* const* d_in, const int* in_sizes, int n_in,
                              void* d_out, int out_size) {
    const float* x = (const float*)d_in[0];
    float* out = (float*)d_out;
    (void)in_sizes; (void)n_in; (void)out_size;

    // 4 x-tiles, 8 y-tiles, 96 images = 3072 blocks of 256 threads
    blur_v4<<<dim3(W_ / TX, H_ / TY, NIMG), 256>>>(x, out);
}

// round 12
// speedup vs baseline: 1.0415x; 1.0415x over previous
#include <cuda_runtime.h>

// GaussianBlur v5c = v3 (proven 56us) + f32x2 column-pair vertical pass.
// depthwise 21x21 Gaussian (sigma=5), reflect pad 10, [32,3,512,512] fp32.
// Tile 128x64 outputs, 256 threads, 5 CTA/SM:
//   phase 1: VERTICAL 21-tap, TWO adjacent columns per thread via LDG.64 +
//            fma.rn.f32x2. Scatter-accumulate into 8 f32x2 accumulators;
//            loads front-batched in 4 chunks (MLP=8) -> 37.9KB smem.
//   phase 2: HORIZONTAL 21-tap from smem (identical to v3: 6x LDS.128
//            conflict-free 4-output windows, FFMA-imm, STG.128).
// (v5c fix: fbits/wpair are __host__ __device__ constexpr so device code may
//  evaluate them; values are still compile-time-folded to immediates.)

#define W_ 512
#define H_ 512
#define NIMG 96
#define PAD 10

#define TX 128
#define TY 64
#define VCOLS   148                 // TX + 2*PAD
#define VSTRIDE 148                 // floats per smem row (592B)
#define QROWS   8                   // v-pass outputs per task
#define VWIN    (QROWS + 2 * PAD)   // 28 rows read per task
#define NPAIR   (VCOLS / 2)         // 74 column pairs
#define NTASK1  (NPAIR * (TY / QROWS))   // 592

typedef unsigned long long u64;

// ---- weights: exp(-(d^2)/50)/12.089199128 (validated rel_err 3.4e-7) ------
#define KWD0  0.01119473
#define KWD1  0.01636989
#define KWD2  0.02299883
#define KWD3  0.03104516
#define KWD4  0.04026340
#define KWD5  0.05017128
#define KWD6  0.06006594
#define KWD7  0.06909227
#define KWD8  0.07635877
#define KWD9  0.08108053
#define KWD10 0.08271847

// constexpr IEEE-754 float encoder (round to nearest; inputs never tie)
__host__ __device__ constexpr unsigned fbits(double x) {
    int e = 0;
    while (x >= 2.0) { x *= 0.5; ++e; }
    while (x < 1.0)  { x *= 2.0; --e; }
    double m = (x - 1.0) * 8388608.0;
    unsigned mi = (unsigned)(m + 0.5);
    unsigned ee = (unsigned)(e + 127);
    if (mi == 8388608u) { mi = 0u; ee += 1u; }
    return (ee << 23) | mi;
}
__host__ __device__ constexpr u64 wpair(double x) {
    u64 b = fbits(x); return (b << 32) | b;
}

// Function-local pair-constant table (compile-time indices after unroll =>
// folded to 64-bit immediates by ptxas).
#define KW2_INIT const u64 KW2[21] = { \
    wpair(KWD0),  wpair(KWD1),  wpair(KWD2),  wpair(KWD3),  wpair(KWD4), \
    wpair(KWD5),  wpair(KWD6),  wpair(KWD7),  wpair(KWD8),  wpair(KWD9), \
    wpair(KWD10), \
    wpair(KWD9),  wpair(KWD8),  wpair(KWD7),  wpair(KWD6),  wpair(KWD5), \
    wpair(KWD4),  wpair(KWD3),  wpair(KWD2),  wpair(KWD1),  wpair(KWD0) }

#define KW_INIT const float KW[21] = { \
    (float)KWD0,  (float)KWD1,  (float)KWD2,  (float)KWD3,  (float)KWD4, \
    (float)KWD5,  (float)KWD6,  (float)KWD7,  (float)KWD8,  (float)KWD9, \
    (float)KWD10, \
    (float)KWD9,  (float)KWD8,  (float)KWD7,  (float)KWD6,  (float)KWD5, \
    (float)KWD4,  (float)KWD3,  (float)KWD2,  (float)KWD1,  (float)KWD0 }

__device__ __forceinline__ int reflect512(int i) {
    i = (i < 0) ? -i : i;
    return (i > 511) ? (1022 - i) : i;
}

__device__ __forceinline__ u64 fma2(u64 a, u64 b, u64 c) {
    u64 d;
    asm("fma.rn.f32x2 %0, %1, %2, %3;" : "=l"(d) : "l"(a), "l"(b), "l"(c));
    return d;
}
__device__ __forceinline__ u64 pack2(float lo, float hi) {
    u64 r;
    asm("mov.b64 %0, {%1, %2};" : "=l"(r) : "f"(lo), "f"(hi));
    return r;
}

// ---- phase-1 body: vertical conv of one column pair, 8 output rows --------
// Scatter form: row j feeds acc[rr] for rr in [max(0,j-20), min(7,j)] with
// weight KW2[j-rr]. Loads front-batched per chunk (8/8/8/4 rows, MLP=8).
template <class F>
__device__ __forceinline__ void vpair_body(F fetch, float* __restrict__ dst) {
    KW2_INIT;
    u64 acc[QROWS];
    #pragma unroll
    for (int r = 0; r < QROWS; ++r) acc[r] = 0ull;

    u64 v[8];
    #pragma unroll
    for (int ch = 0; ch < 4; ++ch) {
        const int base = ch * 8;
        const int nrow = (ch == 3) ? 4 : 8;
        #pragma unroll
        for (int j = 0; j < 8; ++j)
            if (j < nrow) v[j] = fetch(base + j);
        #pragma unroll
        for (int j = 0; j < 8; ++j) {
            if (j < nrow) {
                const int J = base + j;
                #pragma unroll
                for (int rr = 0; rr < QROWS; ++rr)
                    if (rr <= J && J - rr <= 20)
                        acc[rr] = fma2(KW2[J - rr], v[j], acc[rr]);
            }
        }
    }
    #pragma unroll
    for (int rr = 0; rr < QROWS; ++rr)
        *reinterpret_cast<u64*>(dst + rr * VSTRIDE) = acc[rr];
}

// Cold path: x and/or y border pairs (reflected, possibly non-adjacent cols).
__device__ __noinline__ void vpair_border(const float* __restrict__ img,
                                          float* __restrict__ dst,
                                          int yb, int gx) {
    const int rl = reflect512(gx), rh = reflect512(gx + 1);
    vpair_body([&](int j) {
        const size_t ro = (size_t)reflect512(yb + j) * W_;
        return pack2(img[ro + rl], img[ro + rh]);
    }, dst);
}

__global__ __launch_bounds__(256, 5)
void blur_v5(const float* __restrict__ in, float* __restrict__ out) {
    KW_INIT;
    __shared__ __align__(16) float Vs[TY * VSTRIDE];   // 37888 B

    const int n   = blockIdx.z;
    const int x0  = blockIdx.x * TX;
    const int y0  = blockIdx.y * TY;
    const int tid = threadIdx.x;

    const float* __restrict__ img = in + (size_t)n * (H_ * W_);

    // ---- Phase 1: vertical conv, gmem -> Vs (592 pair-tasks) --------------
    #pragma unroll 1
    for (int tau = tid; tau < NTASK1; tau += 256) {
        const int q  = tau / NPAIR;            // 0..7 (y-chunk)
        const int pr = tau - q * NPAIR;        // 0..73 (column pair)
        const int gx = x0 - PAD + 2 * pr;
        const int yb = y0 + q * QROWS - PAD;
        float* dst = Vs + (q * QROWS) * VSTRIDE + 2 * pr;

        if (gx >= 0 && gx + 1 < W_ && yb >= 0 && yb + VWIN <= H_) {
            const u64* __restrict__ p =
                reinterpret_cast<const u64*>(img + (size_t)yb * W_ + gx);
            vpair_body([&](int j) { return p[(size_t)j * (W_ / 2)]; }, dst);
        } else {
            vpair_border(img, dst, yb, gx);
        }
    }
    __syncthreads();

    // ---- Phase 2: horizontal conv, Vs -> gmem (identical to v3) -----------
    // Warp = one row (stride 8), lane g -> outputs [4g..4g+3] from window
    // Vs[r][4g..4g+23]: 6x LDS.128 at 16B-stride starts, conflict-free.
    float* __restrict__ outimg = out + (size_t)n * (H_ * W_);
    const int g  = tid & 31;
    const int r0 = tid >> 5;

    #pragma unroll
    for (int i = 0; i < 8; ++i) {
        const int r = r0 + i * 8;
        const float* __restrict__ src = Vs + r * VSTRIDE + 4 * g;

        float wv[24];
        #pragma unroll
        for (int j = 0; j < 6; ++j) {
            float4 t = *reinterpret_cast<const float4*>(src + 4 * j);
            wv[4 * j + 0] = t.x; wv[4 * j + 1] = t.y;
            wv[4 * j + 2] = t.z; wv[4 * j + 3] = t.w;
        }

        float h0 = 0.f, h1 = 0.f, h2 = 0.f, h3 = 0.f;
        #pragma unroll
        for (int k = 0; k < 21; ++k) {
            const float w = KW[k];
            h0 = fmaf(w, wv[k + 0], h0);
            h1 = fmaf(w, wv[k + 1], h1);
            h2 = fmaf(w, wv[k + 2], h2);
            h3 = fmaf(w, wv[k + 3], h3);
        }
        *reinterpret_cast<float4*>(outimg + (size_t)(y0 + r) * W_ + x0 + 4 * g)
            = make_float4(h0, h1, h2, h3);
    }
}

extern "C" void kernel_launch(void* const* d_in, const int* in_sizes, int n_in,
                              void* d_out, int out_size) {
    const float* x = (const float*)d_in[0];
    float* out = (float*)d_out;
    (void)in_sizes; (void)n_in; (void)out_size;

    blur_v5<<<dim3(W_ / TX, H_ / TY, NIMG), 256>>>(x, out);
}

// round 13
// speedup vs baseline: 1.2269x; 1.1780x over previous
#include <cuda_runtime.h>

// GaussianBlur v6 = v3 (proven 56us) with phase-1 load-balance + halo fixes.
// depthwise 21x21 Gaussian (sigma=5), reflect pad 10, [32,3,512,512] fp32.
// Tile 128x64 outputs, 320 threads, 4 CTA/SM:
//   phase 1: VERTICAL 21-tap from gmem. 296 column-tasks (148 cols x 2
//            y-halves of 32 rows) -> EXACTLY one round over 320 threads.
//            Each task: two front-batched register windows (36 rows -> 16
//            outputs, then 16 more rows -> 16 outputs). Dense coalesced
//            column loads, 1.625 LDG/output. Result -> 37.9KB smem.
//   phase 2: HORIZONTAL 21-tap from smem (v3 pattern: 6x LDS.128
//            conflict-free 4-output windows, FFMA-imm, STG.128); 10 warps
//            cover 64 rows in <=7 guarded iterations.

#define W_ 512
#define H_ 512
#define NIMG 96
#define PAD 10

#define TX 128
#define TY 64
#define VCOLS   148                 // TX + 2*PAD
#define VSTRIDE 148                 // floats per smem row (592B)
#define QROWS   32                  // v-pass outputs per task
#define VWIN    (QROWS + 2 * PAD)   // 52 rows read per task
#define NTASK1  (VCOLS * (TY / QROWS))   // 296 tasks (<= 320 threads)
#define NTHR    320

// 1D separable weights (validated rel_err 3.4e-7): exp(-(d^2)/50)/12.089199128
#define KW_INIT const float KW[21] = { \
    0.01119473f, 0.01636989f, 0.02299883f, 0.03104516f, 0.04026340f, \
    0.05017128f, 0.06006594f, 0.06909227f, 0.07635877f, 0.08108053f, \
    0.08271847f, \
    0.08108053f, 0.07635877f, 0.06909227f, 0.06006594f, 0.05017128f, \
    0.04026340f, 0.03104516f, 0.02299883f, 0.01636989f, 0.01119473f }

__device__ __forceinline__ int reflect512(int i) {
    // jnp.pad mode="reflect": -k -> k, 511+k -> 511-k (single reflection)
    i = (i < 0) ? -i : i;
    return (i > 511) ? (1022 - i) : i;
}

// ---- Phase-1 task: vertical conv of one column, 32 output rows ------------
// Window 1: rows 0..35 (front-batched, MLP=36) -> outputs 0..15.
// Slide:    rows 36..51 into slots 0..15 (front-batched, MLP=16)
//           -> outputs 16..31 (slot(j) = j<36 ? j : j-36, compile-time).
template <bool INTERIOR>
__device__ __forceinline__ void vtask32(const float* __restrict__ img,
                                        float* __restrict__ dst,
                                        int yb, int gx) {
    KW_INIT;
    const float* __restrict__ p =
        img + (size_t)(INTERIOR ? yb : 0) * W_ + gx;

    float v[36];
    #pragma unroll
    for (int j = 0; j < 36; ++j)
        v[j] = INTERIOR ? p[j * W_]
                        : img[(size_t)reflect512(yb + j) * W_ + gx];

    #pragma unroll
    for (int rr = 0; rr < 16; ++rr) {
        float a = 0.f;
        #pragma unroll
        for (int k = 0; k < 21; ++k)
            a = fmaf(KW[k], v[rr + k], a);
        dst[rr * VSTRIDE] = a;                 // conflict-free STS
    }

    #pragma unroll
    for (int j = 0; j < 16; ++j)
        v[j] = INTERIOR ? p[(36 + j) * W_]
                        : img[(size_t)reflect512(yb + 36 + j) * W_ + gx];

    #pragma unroll
    for (int rr = 16; rr < 32; ++rr) {
        float a = 0.f;
        #pragma unroll
        for (int k = 0; k < 21; ++k) {
            const int j = rr + k;              // 16..51, compile-time
            a = fmaf(KW[k], v[(j < 36) ? j : (j - 36)], a);
        }
        dst[rr * VSTRIDE] = a;
    }
}

// Cold path (y-border tiles only): keep out of the hot instruction stream.
__device__ __noinline__ void vtask32_border(const float* __restrict__ img,
                                            float* __restrict__ dst,
                                            int yb, int gx) {
    vtask32<false>(img, dst, yb, gx);
}

__global__ __launch_bounds__(NTHR, 4)
void blur_v6(const float* __restrict__ in, float* __restrict__ out) {
    KW_INIT;
    __shared__ __align__(16) float Vs[TY * VSTRIDE];   // 37888 B

    const int n   = blockIdx.z;
    const int x0  = blockIdx.x * TX;
    const int y0  = blockIdx.y * TY;
    const int tid = threadIdx.x;

    const float* __restrict__ img = in + (size_t)n * (H_ * W_);

    // ---- Phase 1: vertical conv, gmem -> Vs. One task per thread. ---------
    if (tid < NTASK1) {
        const int q  = (tid >= VCOLS) ? 1 : 0;   // NTASK1 == 2*VCOLS
        const int c  = tid - q * VCOLS;
        const int gx = reflect512(x0 - PAD + c);
        const int yb = y0 + q * QROWS - PAD;
        float* dst = Vs + (q * QROWS) * VSTRIDE + c;
        if (yb >= 0 && yb + VWIN <= H_)
            vtask32<true>(img, dst, yb, gx);
        else
            vtask32_border(img, dst, yb, gx);
    }
    __syncthreads();

    // ---- Phase 2: horizontal conv, Vs -> gmem (v3 pattern) ----------------
    // Warp wp handles rows {wp, wp+10, ...}; lane g -> outputs [4g..4g+3]
    // from window Vs[r][4g..4g+23]: 6x LDS.128 at 16B-stride starts
    // (conflict-free phases), STG.128 dense.
    float* __restrict__ outimg = out + (size_t)n * (H_ * W_);
    const int g  = tid & 31;
    const int wp = tid >> 5;       // 0..9

    #pragma unroll
    for (int i = 0; i < 7; ++i) {
        const int r = wp + 10 * i;
        if (r < TY) {
            const float* __restrict__ src = Vs + r * VSTRIDE + 4 * g;

            float wv[24];
            #pragma unroll
            for (int j = 0; j < 6; ++j) {
                float4 t = *reinterpret_cast<const float4*>(src + 4 * j);
                wv[4 * j + 0] = t.x; wv[4 * j + 1] = t.y;
                wv[4 * j + 2] = t.z; wv[4 * j + 3] = t.w;
            }

            float h0 = 0.f, h1 = 0.f, h2 = 0.f, h3 = 0.f;
            #pragma unroll
            for (int k = 0; k < 21; ++k) {
                const float w = KW[k];
                h0 = fmaf(w, wv[k + 0], h0);
                h1 = fmaf(w, wv[k + 1], h1);
                h2 = fmaf(w, wv[k + 2], h2);
                h3 = fmaf(w, wv[k + 3], h3);
            }
            *reinterpret_cast<float4*>(outimg + (size_t)(y0 + r) * W_ + x0 + 4 * g)
                = make_float4(h0, h1, h2, h3);
        }
    }
}

extern "C" void kernel_launch(void* const* d_in, const int* in_sizes, int n_in,
                              void* d_out, int out_size) {
    const float* x = (const float*)d_in[0];
    float* out = (float*)d_out;
    (void)in_sizes; (void)n_in; (void)out_size;

    // 4 x-tiles, 8 y-tiles, 96 images = 3072 blocks of 320 threads
    blur_v6<<<dim3(W_ / TX, H_ / TY, NIMG), NTHR>>>(x, out);
}